// round 5
// baseline (speedup 1.0000x reference)
#include <cuda_runtime.h>
#include <cstdint>

// ---------------------------------------------------------------------------
// Problem constants
// ---------------------------------------------------------------------------
#define NN_MAX 25000
#define NE_MAX 200000
#define HDIM   192
#define OUTF   64

// scratch layout (floats)
constexpr size_t OFF_NR  = 0;
constexpr size_t OFF_NI  = OFF_NR  + (size_t)NN_MAX * 64;
constexpr size_t OFF_ER  = OFF_NI  + (size_t)NN_MAX * 64;
constexpr size_t OFF_EI  = OFF_ER  + (size_t)NE_MAX * 64;
constexpr size_t OFF_NSR = OFF_EI  + (size_t)NE_MAX * 64;
constexpr size_t OFF_ESR = OFF_NSR + (size_t)NN_MAX * 64;
constexpr size_t OFF_NSI = OFF_ESR + (size_t)NN_MAX * 64;
constexpr size_t OFF_ESI = OFF_NSI + (size_t)NN_MAX * 64;
constexpr size_t SCRATCH_FLOATS = OFF_ESI + (size_t)NN_MAX * 64;

__device__ __align__(256) float g_scratch[SCRATCH_FLOATS];
__device__ int g_is64;

// ---------------------------------------------------------------------------
// f32x2 helpers (packed fp32 pair: .x = real channel, .y = imag channel)
// ---------------------------------------------------------------------------
__device__ __forceinline__ unsigned long long pack2(float a, float b) {
    unsigned long long r;
    asm("mov.b64 %0, {%1,%2};" : "=l"(r) : "f"(a), "f"(b));
    return r;
}
__device__ __forceinline__ void unpack2(unsigned long long v, float& a, float& b) {
    asm("mov.b64 {%0,%1}, %2;" : "=f"(a), "=f"(b) : "l"(v));
}
__device__ __forceinline__ void fma2(unsigned long long& d,
                                     unsigned long long a, unsigned long long b) {
    asm("fma.rn.f32x2 %0, %1, %2, %0;" : "+l"(d) : "l"(a), "l"(b));
}
__device__ __forceinline__ void red_add_v4(float* p, float4 v) {
    asm volatile("red.global.add.v4.f32 [%0], {%1,%2,%3,%4};"
                 :: "l"(p), "f"(v.x), "f"(v.y), "f"(v.z), "f"(v.w) : "memory");
}

// ---------------------------------------------------------------------------
// edge_index dtype detection (int64 vs int32)
// ---------------------------------------------------------------------------
__global__ void detect_kernel(const unsigned int* __restrict__ w) {
    unsigned int v = w[2 * threadIdx.x + 1] | w[2 * threadIdx.x + 65];
    unsigned int any = __ballot_sync(0xffffffffu, v != 0u);
    if (threadIdx.x == 0) g_is64 = (any == 0u) ? 1 : 0;
}

__device__ __forceinline__ int eidx_get(const void* __restrict__ p, int i) {
    if (g_is64) return (int)((const long long*)p)[i];
    return ((const int*)p)[i];
}

// ---------------------------------------------------------------------------
// zero aggregation buffers
// ---------------------------------------------------------------------------
__global__ void zero_kernel(float4* __restrict__ p, int n4) {
    int i = blockIdx.x * blockDim.x + threadIdx.x;
    if (i < n4) p[i] = make_float4(0.f, 0.f, 0.f, 0.f);
}

// ---------------------------------------------------------------------------
// lin64: Y = X @ W^T + b for both channels packed as f32x2.
// ---------------------------------------------------------------------------
constexpr int LIN_SMEM = 64 * 64 * 8 + 64 * 65 * 4;

__global__ __launch_bounds__(256) void lin64_kernel(
    int M,
    const float* __restrict__ Xa, const float* __restrict__ Xb,
    const float* __restrict__ W,  const float* __restrict__ bias,
    float* __restrict__ Ya, float* __restrict__ Yb)
{
    extern __shared__ char smraw[];
    unsigned long long* Xs = (unsigned long long*)smraw;   // [64][64]
    float* Ws = (float*)(Xs + 64 * 64);                    // [64][65]

    int tid = threadIdx.x;
    int r0  = blockIdx.x * 64;

    for (int i = tid; i < 4096; i += 256) {
        int n = i >> 6, k = i & 63;
        Ws[n * 65 + k] = W[i];
    }
    for (int i = tid; i < 4096; i += 256) {
        int r = i >> 6, k = i & 63, gr = r0 + r;
        float a = 0.f, b = 0.f;
        if (gr < M) { a = Xa[gr * 64 + k]; b = Xb[gr * 64 + k]; }
        Xs[i] = pack2(a, b);
    }
    __syncthreads();

    int tx = tid & 15, ty = tid >> 4;
    unsigned long long acc[4][4];
#pragma unroll
    for (int j = 0; j < 4; j++) {
        float bv = bias[tx + 16 * j];
        unsigned long long pb = pack2(bv, bv);
#pragma unroll
        for (int i = 0; i < 4; i++) acc[i][j] = pb;
    }

#pragma unroll 8
    for (int k = 0; k < 64; k++) {
        unsigned long long xv[4], wv[4];
#pragma unroll
        for (int i = 0; i < 4; i++) xv[i] = Xs[(ty * 4 + i) * 64 + k];
#pragma unroll
        for (int j = 0; j < 4; j++) {
            float w = Ws[(tx + 16 * j) * 65 + k];
            wv[j] = pack2(w, w);
        }
#pragma unroll
        for (int i = 0; i < 4; i++)
#pragma unroll
            for (int j = 0; j < 4; j++) fma2(acc[i][j], xv[i], wv[j]);
    }

#pragma unroll
    for (int i = 0; i < 4; i++) {
        int gr = r0 + ty * 4 + i;
        if (gr < M) {
#pragma unroll
            for (int j = 0; j < 4; j++) {
                float a, b;
                unpack2(acc[i][j], a, b);
                Ya[gr * 64 + tx + 16 * j] = a;
                Yb[gr * 64 + tx + 16 * j] = b;
            }
        }
    }
}

// ---------------------------------------------------------------------------
// scatter: for each edge e: ns[row] += n[col]; es[row] += e  (real & imag)
// 16 threads per edge, 4 features each; vectorized red.global.add.v4.f32
// ---------------------------------------------------------------------------
__global__ __launch_bounds__(256) void scatter_kernel(
    int NE, const void* __restrict__ eidx,
    const float* __restrict__ nr, const float* __restrict__ ni,
    const float* __restrict__ er, const float* __restrict__ ei,
    float* __restrict__ nsr, float* __restrict__ esr,
    float* __restrict__ nsi, float* __restrict__ esi)
{
    int gid = blockIdx.x * blockDim.x + threadIdx.x;
    int e = gid >> 4;
    if (e >= NE) return;
    int q = (gid & 15) * 4;
    int row = eidx_get(eidx, 2 * e);
    int col = eidx_get(eidx, 2 * e + 1);

    const float4 a = *(const float4*)(nr + col * 64 + q);
    const float4 b = *(const float4*)(er + e   * 64 + q);
    const float4 c = *(const float4*)(ni + col * 64 + q);
    const float4 d = *(const float4*)(ei + e   * 64 + q);

    red_add_v4(nsr + row * 64 + q, a);
    red_add_v4(esr + row * 64 + q, b);
    red_add_v4(nsi + row * 64 + q, c);
    red_add_v4(esi + row * 64 + q, d);
}

// ---------------------------------------------------------------------------
// Fused MLP: 3x (192->192 + LeakyReLU) + (192->64), real+imag packed f32x2.
// MODE 0 (node): x = [s0[r], s1[r], s2[r]]       (nr, ns, es)
// MODE 1 (edge): x = [s0[e], s1[row(e)], s1[col(e)]]
// 64 rows / block, 256 threads laid out as 32 tx x 8 ty;
// thread tile 8 rows x 6 cols (warp = one ty -> xv loads fully broadcast).
// 128-bit smem loads carry two k-steps per instruction.
// smem: Xs [64][192] ull + Wc [192][18] ull (k-chunk, pre-splatted f32x2)
// ---------------------------------------------------------------------------
constexpr int MLP_SMEM = (64 * HDIM + HDIM * 18) * 8;

template <int MODE>
__global__ __launch_bounds__(256) void mlp_kernel(
    int M,
    const float* __restrict__ s0r, const float* __restrict__ s0i,
    const float* __restrict__ s1r, const float* __restrict__ s1i,
    const float* __restrict__ s2r, const float* __restrict__ s2i,
    const void* __restrict__ eidx,
    const float* __restrict__ W,  const float* __restrict__ B,
    const float* __restrict__ alpha,
    const float* __restrict__ Wout, const float* __restrict__ bout,
    float* __restrict__ outR, float* __restrict__ outI)
{
    extern __shared__ char smraw[];
    unsigned long long* Xs = (unsigned long long*)smraw;   // [64][192]
    unsigned long long* Wc = Xs + 64 * HDIM;               // [192][18]

    int tid = threadIdx.x;
    int r0  = blockIdx.x * 64;

    // ---- fill activation tile (gather + pack) ----
    for (int idx = tid; idx < 64 * HDIM; idx += 256) {
        int r = idx / HDIM, k = idx - r * HDIM;
        int gr = r0 + r;
        float a = 0.f, b = 0.f;
        if (gr < M) {
            int src = k >> 6, f = k & 63;
            if (MODE == 0) {
                const float* pr = (src == 0) ? s0r : (src == 1 ? s1r : s2r);
                const float* pi = (src == 0) ? s0i : (src == 1 ? s1i : s2i);
                a = pr[gr * 64 + f];
                b = pi[gr * 64 + f];
            } else {
                if (src == 0) {
                    a = s0r[gr * 64 + f];
                    b = s0i[gr * 64 + f];
                } else {
                    int node = eidx_get(eidx, 2 * gr + (src - 1)); // 1->row, 2->col
                    a = s1r[node * 64 + f];
                    b = s1i[node * 64 + f];
                }
            }
        }
        Xs[idx] = pack2(a, b);
    }

    int tx = tid & 31, ty = tid >> 5;   // warp = single ty

    // ---- 3 hidden layers ----
    for (int l = 0; l < 3; l++) {
        const float* Wl = W + l * HDIM * HDIM;
        const float* bl = B + l * HDIM;
        float al = alpha[l];

        unsigned long long acc[8][6];
#pragma unroll
        for (int j = 0; j < 6; j++) {
            float bv = bl[tx + 32 * j];
            unsigned long long pb = pack2(bv, bv);
#pragma unroll
            for (int i = 0; i < 8; i++) acc[i][j] = pb;
        }

        for (int kt = 0; kt < HDIM; kt += 16) {
            __syncthreads();
            // fill Wc chunk: [192][16] splatted, pad to 18
            for (int idx = tid; idx < HDIM * 8; idx += 256) {
                int n = idx >> 3, kp = (idx & 7) * 2;
                float2 w = *(const float2*)(Wl + n * HDIM + kt + kp);
                ulonglong2 s;
                s.x = pack2(w.x, w.x);
                s.y = pack2(w.y, w.y);
                *(ulonglong2*)(Wc + n * 18 + kp) = s;
            }
            __syncthreads();
#pragma unroll
            for (int kl = 0; kl < 16; kl += 2) {
                ulonglong2 xv[8], wv[6];
#pragma unroll
                for (int i = 0; i < 8; i++)
                    xv[i] = *(const ulonglong2*)(Xs + (ty * 8 + i) * HDIM + kt + kl);
#pragma unroll
                for (int j = 0; j < 6; j++)
                    wv[j] = *(const ulonglong2*)(Wc + (tx + 32 * j) * 18 + kl);
#pragma unroll
                for (int i = 0; i < 8; i++)
#pragma unroll
                    for (int j = 0; j < 6; j++) {
                        fma2(acc[i][j], xv[i].x, wv[j].x);
                        fma2(acc[i][j], xv[i].y, wv[j].y);
                    }
            }
        }

        __syncthreads();
#pragma unroll
        for (int i = 0; i < 8; i++)
#pragma unroll
            for (int j = 0; j < 6; j++) {
                float a, b;
                unpack2(acc[i][j], a, b);
                a = (a >= 0.f) ? a : al * a;
                b = (b >= 0.f) ? b : al * b;
                Xs[(ty * 8 + i) * HDIM + tx + 32 * j] = pack2(a, b);
            }
    }

    // ---- output layer 192 -> 64 : tile 8 rows x 2 cols ----
    unsigned long long oacc[8][2];
#pragma unroll
    for (int j = 0; j < 2; j++) {
        float bv = bout[tx + 32 * j];
        unsigned long long pb = pack2(bv, bv);
#pragma unroll
        for (int i = 0; i < 8; i++) oacc[i][j] = pb;
    }

    for (int kt = 0; kt < HDIM; kt += 16) {
        __syncthreads();
        for (int idx = tid; idx < OUTF * 8; idx += 256) {
            int n = idx >> 3, kp = (idx & 7) * 2;
            float2 w = *(const float2*)(Wout + n * HDIM + kt + kp);
            ulonglong2 s;
            s.x = pack2(w.x, w.x);
            s.y = pack2(w.y, w.y);
            *(ulonglong2*)(Wc + n * 18 + kp) = s;
        }
        __syncthreads();
#pragma unroll
        for (int kl = 0; kl < 16; kl += 2) {
            ulonglong2 xv[8], wv[2];
#pragma unroll
            for (int i = 0; i < 8; i++)
                xv[i] = *(const ulonglong2*)(Xs + (ty * 8 + i) * HDIM + kt + kl);
#pragma unroll
            for (int j = 0; j < 2; j++)
                wv[j] = *(const ulonglong2*)(Wc + (tx + 32 * j) * 18 + kl);
#pragma unroll
            for (int i = 0; i < 8; i++)
#pragma unroll
                for (int j = 0; j < 2; j++) {
                    fma2(oacc[i][j], xv[i].x, wv[j].x);
                    fma2(oacc[i][j], xv[i].y, wv[j].y);
                }
        }
    }

#pragma unroll
    for (int i = 0; i < 8; i++) {
        int gr = r0 + ty * 8 + i;
        if (gr < M) {
#pragma unroll
            for (int j = 0; j < 2; j++) {
                float a, b;
                unpack2(oacc[i][j], a, b);
                outR[gr * 64 + tx + 32 * j] = a;
                outI[gr * 64 + tx + 32 * j] = b;
            }
        }
    }
}

// ---------------------------------------------------------------------------
// launch
// ---------------------------------------------------------------------------
extern "C" void kernel_launch(void* const* d_in, const int* in_sizes, int n_in,
                              void* d_out, int out_size)
{
    const float* node_real = (const float*)d_in[0];
    const float* node_imag = (const float*)d_in[1];
    const float* edge_real = (const float*)d_in[2];
    const float* edge_imag = (const float*)d_in[3];
    const void*  edge_index = d_in[4];
    const float* Wn = (const float*)d_in[5];
    const float* bn = (const float*)d_in[6];
    const float* We = (const float*)d_in[7];
    const float* be = (const float*)d_in[8];
    const float* node_W    = (const float*)d_in[9];
    const float* node_b    = (const float*)d_in[10];
    const float* node_alpha= (const float*)d_in[11];
    const float* node_outW = (const float*)d_in[12];
    const float* node_outb = (const float*)d_in[13];
    const float* edge_W    = (const float*)d_in[14];
    const float* edge_b    = (const float*)d_in[15];
    const float* edge_alpha= (const float*)d_in[16];
    const float* edge_outW = (const float*)d_in[17];
    const float* edge_outb = (const float*)d_in[18];

    int Nn = in_sizes[0] / 64;
    int Ne = in_sizes[2] / 64;

    float* scratch = nullptr;
    cudaGetSymbolAddress((void**)&scratch, g_scratch);
    float* nr  = scratch + OFF_NR;
    float* ni  = scratch + OFF_NI;
    float* er  = scratch + OFF_ER;
    float* ei  = scratch + OFF_EI;
    float* nsr = scratch + OFF_NSR;
    float* esr = scratch + OFF_ESR;
    float* nsi = scratch + OFF_NSI;
    float* esi = scratch + OFF_ESI;

    float* outp = (float*)d_out;
    float* hr   = outp;
    float* hi   = outp + (size_t)Nn * 64;
    float* outr = outp + (size_t)2 * Nn * 64;
    float* outi = outr + (size_t)Ne * 64;

    cudaFuncSetAttribute(lin64_kernel, cudaFuncAttributeMaxDynamicSharedMemorySize, LIN_SMEM);
    cudaFuncSetAttribute(mlp_kernel<0>, cudaFuncAttributeMaxDynamicSharedMemorySize, MLP_SMEM);
    cudaFuncSetAttribute(mlp_kernel<1>, cudaFuncAttributeMaxDynamicSharedMemorySize, MLP_SMEM);

    // 1) detect edge_index dtype
    detect_kernel<<<1, 32>>>((const unsigned int*)edge_index);

    // 2) zero aggregation region
    int aggN4 = (int)(4 * (size_t)NN_MAX * 64 / 4);
    zero_kernel<<<(aggN4 + 255) / 256, 256>>>((float4*)nsr, aggN4);

    // 3) node / edge input linears (real+imag fused per f32x2 lane)
    lin64_kernel<<<(Nn + 63) / 64, 256, LIN_SMEM>>>(Nn, node_real, node_imag, Wn, bn, nr, ni);
    lin64_kernel<<<(Ne + 63) / 64, 256, LIN_SMEM>>>(Ne, edge_real, edge_imag, We, be, er, ei);

    // 4) edge scatter-aggregation (vector red)
    int sthreads = Ne * 16;
    scatter_kernel<<<(sthreads + 255) / 256, 256>>>(Ne, edge_index, nr, ni, er, ei,
                                                    nsr, esr, nsi, esi);

    // 5) node MLP -> hr, hi (directly into d_out)
    mlp_kernel<0><<<(Nn + 63) / 64, 256, MLP_SMEM>>>(
        Nn, nr, ni, nsr, nsi, esr, esi, nullptr,
        node_W, node_b, node_alpha, node_outW, node_outb, hr, hi);

    // 6) edge MLP (gathers hr/hi by row/col) -> outr, outi
    mlp_kernel<1><<<(Ne + 63) / 64, 256, MLP_SMEM>>>(
        Ne, er, ei, hr, hi, hr, hi, edge_index,
        edge_W, edge_b, edge_alpha, edge_outW, edge_outb, outr, outi);
}

// round 8
// speedup vs baseline: 1.7979x; 1.7979x over previous
#include <cuda_runtime.h>
#include <cstdint>

// ---------------------------------------------------------------------------
// Problem constants
// ---------------------------------------------------------------------------
#define NN_MAX 25000
#define NE_MAX 200000
#define HDIM   192
#define OUTF   64

// scratch layout (floats)
constexpr size_t OFF_NR  = 0;
constexpr size_t OFF_NI  = OFF_NR  + (size_t)NN_MAX * 64;
constexpr size_t OFF_ER  = OFF_NI  + (size_t)NN_MAX * 64;
constexpr size_t OFF_EI  = OFF_ER  + (size_t)NE_MAX * 64;
constexpr size_t OFF_NSR = OFF_EI  + (size_t)NE_MAX * 64;
constexpr size_t OFF_ESR = OFF_NSR + (size_t)NN_MAX * 64;
constexpr size_t OFF_NSI = OFF_ESR + (size_t)NN_MAX * 64;
constexpr size_t OFF_ESI = OFF_NSI + (size_t)NN_MAX * 64;
constexpr size_t SCRATCH_FLOATS = OFF_ESI + (size_t)NN_MAX * 64;

__device__ __align__(256) float g_scratch[SCRATCH_FLOATS];
__device__ int g_is64;

// ---------------------------------------------------------------------------
// f32x2 helpers (packed fp32 pair: .x = real channel, .y = imag channel)
// ---------------------------------------------------------------------------
__device__ __forceinline__ unsigned long long pack2(float a, float b) {
    unsigned long long r;
    asm("mov.b64 %0, {%1,%2};" : "=l"(r) : "f"(a), "f"(b));
    return r;
}
__device__ __forceinline__ void unpack2(unsigned long long v, float& a, float& b) {
    asm("mov.b64 {%0,%1}, %2;" : "=f"(a), "=f"(b) : "l"(v));
}
__device__ __forceinline__ void fma2(unsigned long long& d,
                                     unsigned long long a, unsigned long long b) {
    asm("fma.rn.f32x2 %0, %1, %2, %0;" : "+l"(d) : "l"(a), "l"(b));
}
__device__ __forceinline__ void red_add_v4(float* p, float4 v) {
    asm volatile("red.global.add.v4.f32 [%0], {%1,%2,%3,%4};"
                 :: "l"(p), "f"(v.x), "f"(v.y), "f"(v.z), "f"(v.w) : "memory");
}

// ---------------------------------------------------------------------------
// edge_index dtype detection (int64 vs int32)
// ---------------------------------------------------------------------------
__global__ void detect_kernel(const unsigned int* __restrict__ w) {
    unsigned int v = w[2 * threadIdx.x + 1] | w[2 * threadIdx.x + 65];
    unsigned int any = __ballot_sync(0xffffffffu, v != 0u);
    if (threadIdx.x == 0) g_is64 = (any == 0u) ? 1 : 0;
}

__device__ __forceinline__ int eidx_get(const void* __restrict__ p, int i) {
    if (g_is64) return (int)((const long long*)p)[i];
    return ((const int*)p)[i];
}

// ---------------------------------------------------------------------------
// zero aggregation buffers
// ---------------------------------------------------------------------------
__global__ void zero_kernel(float4* __restrict__ p, int n4) {
    int i = blockIdx.x * blockDim.x + threadIdx.x;
    if (i < n4) p[i] = make_float4(0.f, 0.f, 0.f, 0.f);
}

// ---------------------------------------------------------------------------
// lin64: Y = X @ W^T + b for both channels packed as f32x2.  (unchanged, proven)
// ---------------------------------------------------------------------------
constexpr int LIN_SMEM = 64 * 64 * 8 + 64 * 65 * 4;

__global__ __launch_bounds__(256) void lin64_kernel(
    int M,
    const float* __restrict__ Xa, const float* __restrict__ Xb,
    const float* __restrict__ W,  const float* __restrict__ bias,
    float* __restrict__ Ya, float* __restrict__ Yb)
{
    extern __shared__ char smraw[];
    unsigned long long* Xs = (unsigned long long*)smraw;   // [64][64]
    float* Ws = (float*)(Xs + 64 * 64);                    // [64][65]

    int tid = threadIdx.x;
    int r0  = blockIdx.x * 64;

    for (int i = tid; i < 4096; i += 256) {
        int n = i >> 6, k = i & 63;
        Ws[n * 65 + k] = W[i];
    }
    for (int i = tid; i < 4096; i += 256) {
        int r = i >> 6, k = i & 63, gr = r0 + r;
        float a = 0.f, b = 0.f;
        if (gr < M) { a = Xa[gr * 64 + k]; b = Xb[gr * 64 + k]; }
        Xs[i] = pack2(a, b);
    }
    __syncthreads();

    int tx = tid & 15, ty = tid >> 4;
    unsigned long long acc[4][4];
#pragma unroll
    for (int j = 0; j < 4; j++) {
        float bv = bias[tx + 16 * j];
        unsigned long long pb = pack2(bv, bv);
#pragma unroll
        for (int i = 0; i < 4; i++) acc[i][j] = pb;
    }

#pragma unroll 8
    for (int k = 0; k < 64; k++) {
        unsigned long long xv[4], wv[4];
#pragma unroll
        for (int i = 0; i < 4; i++) xv[i] = Xs[(ty * 4 + i) * 64 + k];
#pragma unroll
        for (int j = 0; j < 4; j++) {
            float w = Ws[(tx + 16 * j) * 65 + k];
            wv[j] = pack2(w, w);
        }
#pragma unroll
        for (int i = 0; i < 4; i++)
#pragma unroll
            for (int j = 0; j < 4; j++) fma2(acc[i][j], xv[i], wv[j]);
    }

#pragma unroll
    for (int i = 0; i < 4; i++) {
        int gr = r0 + ty * 4 + i;
        if (gr < M) {
#pragma unroll
            for (int j = 0; j < 4; j++) {
                float a, b;
                unpack2(acc[i][j], a, b);
                Ya[gr * 64 + tx + 16 * j] = a;
                Yb[gr * 64 + tx + 16 * j] = b;
            }
        }
    }
}

// ---------------------------------------------------------------------------
// scatter: for each edge e: ns[row] += n[col]; es[row] += e  (real & imag)
// 16 threads per edge, 4 features each; vectorized red.global.add.v4.f32
// ---------------------------------------------------------------------------
__global__ __launch_bounds__(256) void scatter_kernel(
    int NE, const void* __restrict__ eidx,
    const float* __restrict__ nr, const float* __restrict__ ni,
    const float* __restrict__ er, const float* __restrict__ ei,
    float* __restrict__ nsr, float* __restrict__ esr,
    float* __restrict__ nsi, float* __restrict__ esi)
{
    int gid = blockIdx.x * blockDim.x + threadIdx.x;
    int e = gid >> 4;
    if (e >= NE) return;
    int q = (gid & 15) * 4;
    int row = eidx_get(eidx, 2 * e);
    int col = eidx_get(eidx, 2 * e + 1);

    const float4 a = *(const float4*)(nr + col * 64 + q);
    const float4 b = *(const float4*)(er + e   * 64 + q);
    const float4 c = *(const float4*)(ni + col * 64 + q);
    const float4 d = *(const float4*)(ei + e   * 64 + q);

    red_add_v4(nsr + row * 64 + q, a);
    red_add_v4(esr + row * 64 + q, b);
    red_add_v4(nsi + row * 64 + q, c);
    red_add_v4(esi + row * 64 + q, d);
}

// ---------------------------------------------------------------------------
// Fused MLP: 3x (192->192 + LeakyReLU) + (192->64), real+imag packed f32x2.
// MODE 0 (node): x = [s0[r], s1[r], s2[r]]       (nr, ns, es)
// MODE 1 (edge): x = [s0[e], s1[row(e)], s1[col(e)]]
//
// 64 rows/block, 256 threads (16tx x 16ty), thread tile 4 rows x 12 cols.
// Weight chunk = 8 k-steps, Wc [192][9] ull (odd stride -> banks 18*tx%32,
// all-distinct for tx<16: conflict-free LDS.64).
// smem/block = 64*192*8 + 192*9*8 = 110,016 B  -> 2 blocks/SM (16 warps).
// __launch_bounds__(256,2) caps regs at 128 so both blocks are resident.
// ---------------------------------------------------------------------------
constexpr int MLP_SMEM = (64 * HDIM + HDIM * 9) * 8;

template <int MODE>
__global__ __launch_bounds__(256, 2) void mlp_kernel(
    int M,
    const float* __restrict__ s0r, const float* __restrict__ s0i,
    const float* __restrict__ s1r, const float* __restrict__ s1i,
    const float* __restrict__ s2r, const float* __restrict__ s2i,
    const void* __restrict__ eidx,
    const float* __restrict__ W,  const float* __restrict__ B,
    const float* __restrict__ alpha,
    const float* __restrict__ Wout, const float* __restrict__ bout,
    float* __restrict__ outR, float* __restrict__ outI)
{
    extern __shared__ char smraw[];
    unsigned long long* Xs = (unsigned long long*)smraw;   // [64][192]
    unsigned long long* Wc = Xs + 64 * HDIM;               // [192][9]

    int tid = threadIdx.x;
    int r0  = blockIdx.x * 64;

    // ---- fill activation tile (gather + pack) ----
    for (int idx = tid; idx < 64 * HDIM; idx += 256) {
        int r = idx / HDIM, k = idx - r * HDIM;
        int gr = r0 + r;
        float a = 0.f, b = 0.f;
        if (gr < M) {
            int src = k >> 6, f = k & 63;
            if (MODE == 0) {
                const float* pr = (src == 0) ? s0r : (src == 1 ? s1r : s2r);
                const float* pi = (src == 0) ? s0i : (src == 1 ? s1i : s2i);
                a = pr[gr * 64 + f];
                b = pi[gr * 64 + f];
            } else {
                if (src == 0) {
                    a = s0r[gr * 64 + f];
                    b = s0i[gr * 64 + f];
                } else {
                    int node = eidx_get(eidx, 2 * gr + (src - 1)); // 1->row, 2->col
                    a = s1r[node * 64 + f];
                    b = s1i[node * 64 + f];
                }
            }
        }
        Xs[idx] = pack2(a, b);
    }

    int tx = tid & 15, ty = tid >> 4;

    // ---- 3 hidden layers ----
    for (int l = 0; l < 3; l++) {
        const float* Wl = W + l * HDIM * HDIM;
        const float* bl = B + l * HDIM;
        float al = alpha[l];

        unsigned long long acc[4][12];
#pragma unroll
        for (int j = 0; j < 12; j++) {
            float bv = bl[tx + 16 * j];
            unsigned long long pb = pack2(bv, bv);
#pragma unroll
            for (int i = 0; i < 4; i++) acc[i][j] = pb;
        }

        for (int kt = 0; kt < HDIM; kt += 8) {
            __syncthreads();               // previous chunk consumed / Xs ready
            // fill Wc chunk: [192][8] splatted, stride 9
            for (int idx = tid; idx < HDIM * 8; idx += 256) {
                int n = idx >> 3, kl = idx & 7;
                float w = Wl[n * HDIM + kt + kl];
                Wc[n * 9 + kl] = pack2(w, w);
            }
            __syncthreads();
#pragma unroll
            for (int kl = 0; kl < 8; kl++) {
                unsigned long long xv[4];
#pragma unroll
                for (int i = 0; i < 4; i++)
                    xv[i] = Xs[(ty * 4 + i) * HDIM + kt + kl];
#pragma unroll
                for (int j = 0; j < 12; j++) {
                    unsigned long long wv = Wc[(tx + 16 * j) * 9 + kl];
#pragma unroll
                    for (int i = 0; i < 4; i++) fma2(acc[i][j], xv[i], wv);
                }
            }
        }

        __syncthreads();
#pragma unroll
        for (int i = 0; i < 4; i++)
#pragma unroll
            for (int j = 0; j < 12; j++) {
                float a, b;
                unpack2(acc[i][j], a, b);
                a = (a >= 0.f) ? a : al * a;
                b = (b >= 0.f) ? b : al * b;
                Xs[(ty * 4 + i) * HDIM + tx + 16 * j] = pack2(a, b);
            }
    }

    // ---- output layer 192 -> 64 : tile 4 rows x 4 cols ----
    unsigned long long oacc[4][4];
#pragma unroll
    for (int j = 0; j < 4; j++) {
        float bv = bout[tx + 16 * j];
        unsigned long long pb = pack2(bv, bv);
#pragma unroll
        for (int i = 0; i < 4; i++) oacc[i][j] = pb;
    }

    for (int kt = 0; kt < HDIM; kt += 8) {
        __syncthreads();
        for (int idx = tid; idx < OUTF * 8; idx += 256) {
            int n = idx >> 3, kl = idx & 7;
            float w = Wout[n * HDIM + kt + kl];
            Wc[n * 9 + kl] = pack2(w, w);
        }
        __syncthreads();
#pragma unroll
        for (int kl = 0; kl < 8; kl++) {
            unsigned long long xv[4];
#pragma unroll
            for (int i = 0; i < 4; i++)
                xv[i] = Xs[(ty * 4 + i) * HDIM + kt + kl];
#pragma unroll
            for (int j = 0; j < 4; j++) {
                unsigned long long wv = Wc[(tx + 16 * j) * 9 + kl];
#pragma unroll
                for (int i = 0; i < 4; i++) fma2(oacc[i][j], xv[i], wv);
            }
        }
    }

#pragma unroll
    for (int i = 0; i < 4; i++) {
        int gr = r0 + ty * 4 + i;
        if (gr < M) {
#pragma unroll
            for (int j = 0; j < 4; j++) {
                float a, b;
                unpack2(oacc[i][j], a, b);
                outR[gr * 64 + tx + 16 * j] = a;
                outI[gr * 64 + tx + 16 * j] = b;
            }
        }
    }
}

// ---------------------------------------------------------------------------
// launch
// ---------------------------------------------------------------------------
extern "C" void kernel_launch(void* const* d_in, const int* in_sizes, int n_in,
                              void* d_out, int out_size)
{
    const float* node_real = (const float*)d_in[0];
    const float* node_imag = (const float*)d_in[1];
    const float* edge_real = (const float*)d_in[2];
    const float* edge_imag = (const float*)d_in[3];
    const void*  edge_index = d_in[4];
    const float* Wn = (const float*)d_in[5];
    const float* bn = (const float*)d_in[6];
    const float* We = (const float*)d_in[7];
    const float* be = (const float*)d_in[8];
    const float* node_W    = (const float*)d_in[9];
    const float* node_b    = (const float*)d_in[10];
    const float* node_alpha= (const float*)d_in[11];
    const float* node_outW = (const float*)d_in[12];
    const float* node_outb = (const float*)d_in[13];
    const float* edge_W    = (const float*)d_in[14];
    const float* edge_b    = (const float*)d_in[15];
    const float* edge_alpha= (const float*)d_in[16];
    const float* edge_outW = (const float*)d_in[17];
    const float* edge_outb = (const float*)d_in[18];

    int Nn = in_sizes[0] / 64;
    int Ne = in_sizes[2] / 64;

    float* scratch = nullptr;
    cudaGetSymbolAddress((void**)&scratch, g_scratch);
    float* nr  = scratch + OFF_NR;
    float* ni  = scratch + OFF_NI;
    float* er  = scratch + OFF_ER;
    float* ei  = scratch + OFF_EI;
    float* nsr = scratch + OFF_NSR;
    float* esr = scratch + OFF_ESR;
    float* nsi = scratch + OFF_NSI;
    float* esi = scratch + OFF_ESI;

    float* outp = (float*)d_out;
    float* hr   = outp;
    float* hi   = outp + (size_t)Nn * 64;
    float* outr = outp + (size_t)2 * Nn * 64;
    float* outi = outr + (size_t)Ne * 64;

    cudaFuncSetAttribute(lin64_kernel, cudaFuncAttributeMaxDynamicSharedMemorySize, LIN_SMEM);
    cudaFuncSetAttribute(mlp_kernel<0>, cudaFuncAttributeMaxDynamicSharedMemorySize, MLP_SMEM);
    cudaFuncSetAttribute(mlp_kernel<1>, cudaFuncAttributeMaxDynamicSharedMemorySize, MLP_SMEM);

    // 1) detect edge_index dtype
    detect_kernel<<<1, 32>>>((const unsigned int*)edge_index);

    // 2) zero aggregation region
    int aggN4 = (int)(4 * (size_t)NN_MAX * 64 / 4);
    zero_kernel<<<(aggN4 + 255) / 256, 256>>>((float4*)nsr, aggN4);

    // 3) node / edge input linears (real+imag fused per f32x2 lane)
    lin64_kernel<<<(Nn + 63) / 64, 256, LIN_SMEM>>>(Nn, node_real, node_imag, Wn, bn, nr, ni);
    lin64_kernel<<<(Ne + 63) / 64, 256, LIN_SMEM>>>(Ne, edge_real, edge_imag, We, be, er, ei);

    // 4) edge scatter-aggregation (vector red)
    int sthreads = Ne * 16;
    scatter_kernel<<<(sthreads + 255) / 256, 256>>>(Ne, edge_index, nr, ni, er, ei,
                                                    nsr, esr, nsi, esi);

    // 5) node MLP -> hr, hi (directly into d_out)
    mlp_kernel<0><<<(Nn + 63) / 64, 256, MLP_SMEM>>>(
        Nn, nr, ni, nsr, nsi, esr, esi, nullptr,
        node_W, node_b, node_alpha, node_outW, node_outb, hr, hi);

    // 6) edge MLP (gathers hr/hi by row/col) -> outr, outi
    mlp_kernel<1><<<(Ne + 63) / 64, 256, MLP_SMEM>>>(
        Ne, er, ei, hr, hi, hr, hi, edge_index,
        edge_W, edge_b, edge_alpha, edge_outW, edge_outb, outr, outi);
}

// round 12
// speedup vs baseline: 3.3201x; 1.8466x over previous
#include <cuda_runtime.h>
#include <cuda_bf16.h>
#include <cstdint>

// ---------------------------------------------------------------------------
// Problem constants
// ---------------------------------------------------------------------------
#define NN_MAX 25000
#define NE_MAX 200000
#define HDIM   192
#define OUTF   64

// scratch layout (floats)
constexpr size_t OFF_NR  = 0;
constexpr size_t OFF_NI  = OFF_NR  + (size_t)NN_MAX * 64;
constexpr size_t OFF_ER  = OFF_NI  + (size_t)NN_MAX * 64;
constexpr size_t OFF_EI  = OFF_ER  + (size_t)NE_MAX * 64;
constexpr size_t OFF_NSR = OFF_EI  + (size_t)NE_MAX * 64;
constexpr size_t OFF_ESR = OFF_NSR + (size_t)NN_MAX * 64;
constexpr size_t OFF_NSI = OFF_ESR + (size_t)NN_MAX * 64;
constexpr size_t OFF_ESI = OFF_NSI + (size_t)NN_MAX * 64;
constexpr size_t SCRATCH_FLOATS = OFF_ESI + (size_t)NN_MAX * 64;

__device__ __align__(256) float g_scratch[SCRATCH_FLOATS];
__device__ int g_is64;

// pre-converted bf16 weights (hi / lo split), [out][in] row-major
constexpr int WOFF_NODE_HID = 0;
constexpr int WOFF_NODE_OUT = WOFF_NODE_HID + 3 * HDIM * HDIM;
constexpr int WOFF_EDGE_HID = WOFF_NODE_OUT + OUTF * HDIM;
constexpr int WOFF_EDGE_OUT = WOFF_EDGE_HID + 3 * HDIM * HDIM;
constexpr int WTOT          = WOFF_EDGE_OUT + OUTF * HDIM;

__device__ __align__(256) __nv_bfloat16 g_wh[WTOT];
__device__ __align__(256) __nv_bfloat16 g_wl[WTOT];

// ---------------------------------------------------------------------------
// helpers
// ---------------------------------------------------------------------------
__device__ __forceinline__ unsigned long long pack2(float a, float b) {
    unsigned long long r;
    asm("mov.b64 %0, {%1,%2};" : "=l"(r) : "f"(a), "f"(b));
    return r;
}
__device__ __forceinline__ void unpack2(unsigned long long v, float& a, float& b) {
    asm("mov.b64 {%0,%1}, %2;" : "=f"(a), "=f"(b) : "l"(v));
}
__device__ __forceinline__ void fma2(unsigned long long& d,
                                     unsigned long long a, unsigned long long b) {
    asm("fma.rn.f32x2 %0, %1, %2, %0;" : "+l"(d) : "l"(a), "l"(b));
}
__device__ __forceinline__ void red_add_v4(float* p, float4 v) {
    asm volatile("red.global.add.v4.f32 [%0], {%1,%2,%3,%4};"
                 :: "l"(p), "f"(v.x), "f"(v.y), "f"(v.z), "f"(v.w) : "memory");
}
__device__ __forceinline__ uint32_t smem_u32(const void* p) {
    uint32_t a;
    asm("{ .reg .u64 t; cvta.to.shared.u64 t, %1; cvt.u32.u64 %0, t; }"
        : "=r"(a) : "l"(p));
    return a;
}
__device__ __forceinline__ void split_bf16(float v, uint16_t& h, uint16_t& l) {
    __nv_bfloat16 hb = __float2bfloat16_rn(v);
    float r = v - __bfloat162float(hb);
    __nv_bfloat16 lb = __float2bfloat16_rn(r);
    h = __bfloat16_as_ushort(hb);
    l = __bfloat16_as_ushort(lb);
}
// warp-level tensor ops (portable PTX, no sm_103a-only features)
__device__ __forceinline__ void ldsm4(uint32_t* r, uint32_t addr) {
    asm volatile("ldmatrix.sync.aligned.m8n8.x4.shared.b16 {%0,%1,%2,%3}, [%4];"
                 : "=r"(r[0]), "=r"(r[1]), "=r"(r[2]), "=r"(r[3]) : "r"(addr));
}
__device__ __forceinline__ void mma16816(float* d, const uint32_t* a, const uint32_t* b) {
    asm volatile("mma.sync.aligned.m16n8k16.row.col.f32.bf16.bf16.f32 "
                 "{%0,%1,%2,%3}, {%4,%5,%6,%7}, {%8,%9}, {%0,%1,%2,%3};"
                 : "+f"(d[0]), "+f"(d[1]), "+f"(d[2]), "+f"(d[3])
                 : "r"(a[0]), "r"(a[1]), "r"(a[2]), "r"(a[3]), "r"(b[0]), "r"(b[1]));
}

// ---------------------------------------------------------------------------
// edge_index dtype detection (int64 vs int32)
// ---------------------------------------------------------------------------
__global__ void detect_kernel(const unsigned int* __restrict__ w) {
    unsigned int v = w[2 * threadIdx.x + 1] | w[2 * threadIdx.x + 65];
    unsigned int any = __ballot_sync(0xffffffffu, v != 0u);
    if (threadIdx.x == 0) g_is64 = (any == 0u) ? 1 : 0;
}
__device__ __forceinline__ int eidx_get(const void* __restrict__ p, int i) {
    if (g_is64) return (int)((const long long*)p)[i];
    return ((const int*)p)[i];
}

// ---------------------------------------------------------------------------
// zero aggregation buffers
// ---------------------------------------------------------------------------
__global__ void zero_kernel(float4* __restrict__ p, int n4) {
    int i = blockIdx.x * blockDim.x + threadIdx.x;
    if (i < n4) p[i] = make_float4(0.f, 0.f, 0.f, 0.f);
}

// ---------------------------------------------------------------------------
// weight pre-conversion: fp32 -> bf16 hi/lo
// ---------------------------------------------------------------------------
__global__ void wconv_kernel(const float* __restrict__ nW, const float* __restrict__ nOW,
                             const float* __restrict__ eW, const float* __restrict__ eOW)
{
    int idx = blockIdx.x * blockDim.x + threadIdx.x;
    if (idx >= WTOT) return;
    float v;
    if (idx < WOFF_NODE_OUT)      v = nW[idx - WOFF_NODE_HID];
    else if (idx < WOFF_EDGE_HID) v = nOW[idx - WOFF_NODE_OUT];
    else if (idx < WOFF_EDGE_OUT) v = eW[idx - WOFF_EDGE_HID];
    else                          v = eOW[idx - WOFF_EDGE_OUT];
    uint16_t h, l;
    split_bf16(v, h, l);
    g_wh[idx] = __ushort_as_bfloat16(h);
    g_wl[idx] = __ushort_as_bfloat16(l);
}

// ---------------------------------------------------------------------------
// lin64 (proven, unchanged)
// ---------------------------------------------------------------------------
constexpr int LIN_SMEM = 64 * 64 * 8 + 64 * 65 * 4;

__global__ __launch_bounds__(256) void lin64_kernel(
    int M,
    const float* __restrict__ Xa, const float* __restrict__ Xb,
    const float* __restrict__ W,  const float* __restrict__ bias,
    float* __restrict__ Ya, float* __restrict__ Yb)
{
    extern __shared__ char smraw[];
    unsigned long long* Xs = (unsigned long long*)smraw;   // [64][64]
    float* Ws = (float*)(Xs + 64 * 64);                    // [64][65]

    int tid = threadIdx.x;
    int r0  = blockIdx.x * 64;

    for (int i = tid; i < 4096; i += 256) {
        int n = i >> 6, k = i & 63;
        Ws[n * 65 + k] = W[i];
    }
    for (int i = tid; i < 4096; i += 256) {
        int r = i >> 6, k = i & 63, gr = r0 + r;
        float a = 0.f, b = 0.f;
        if (gr < M) { a = Xa[gr * 64 + k]; b = Xb[gr * 64 + k]; }
        Xs[i] = pack2(a, b);
    }
    __syncthreads();

    int tx = tid & 15, ty = tid >> 4;
    unsigned long long acc[4][4];
#pragma unroll
    for (int j = 0; j < 4; j++) {
        float bv = bias[tx + 16 * j];
        unsigned long long pb = pack2(bv, bv);
#pragma unroll
        for (int i = 0; i < 4; i++) acc[i][j] = pb;
    }

#pragma unroll 8
    for (int k = 0; k < 64; k++) {
        unsigned long long xv[4], wv[4];
#pragma unroll
        for (int i = 0; i < 4; i++) xv[i] = Xs[(ty * 4 + i) * 64 + k];
#pragma unroll
        for (int j = 0; j < 4; j++) {
            float w = Ws[(tx + 16 * j) * 65 + k];
            wv[j] = pack2(w, w);
        }
#pragma unroll
        for (int i = 0; i < 4; i++)
#pragma unroll
            for (int j = 0; j < 4; j++) fma2(acc[i][j], xv[i], wv[j]);
    }

#pragma unroll
    for (int i = 0; i < 4; i++) {
        int gr = r0 + ty * 4 + i;
        if (gr < M) {
#pragma unroll
            for (int j = 0; j < 4; j++) {
                float a, b;
                unpack2(acc[i][j], a, b);
                Ya[gr * 64 + tx + 16 * j] = a;
                Yb[gr * 64 + tx + 16 * j] = b;
            }
        }
    }
}

// ---------------------------------------------------------------------------
// scatter (proven, unchanged)
// ---------------------------------------------------------------------------
__global__ __launch_bounds__(256) void scatter_kernel(
    int NE, const void* __restrict__ eidx,
    const float* __restrict__ nr, const float* __restrict__ ni,
    const float* __restrict__ er, const float* __restrict__ ei,
    float* __restrict__ nsr, float* __restrict__ esr,
    float* __restrict__ nsi, float* __restrict__ esi)
{
    int gid = blockIdx.x * blockDim.x + threadIdx.x;
    int e = gid >> 4;
    if (e >= NE) return;
    int q = (gid & 15) * 4;
    int row = eidx_get(eidx, 2 * e);
    int col = eidx_get(eidx, 2 * e + 1);

    const float4 a = *(const float4*)(nr + col * 64 + q);
    const float4 b = *(const float4*)(er + e   * 64 + q);
    const float4 c = *(const float4*)(ni + col * 64 + q);
    const float4 d = *(const float4*)(ei + e   * 64 + q);

    red_add_v4(nsr + row * 64 + q, a);
    red_add_v4(esr + row * 64 + q, b);
    red_add_v4(nsi + row * 64 + q, c);
    red_add_v4(esi + row * 64 + q, d);
}

// ---------------------------------------------------------------------------
// mma.sync fused MLP: 3x(192->192 + LeakyReLU) + (192->64)
// bf16 hi/lo split; fp32 accum in registers. Tile = 128 rows of Meff=2*M.
// 8 warps as 2(m) x 4(n). Hidden: warp tile 64x48 (4 m-tiles x 6 n-tiles).
// A in smem: [128][stride 200] bf16, hi plane + lo plane  (conflict-free LDSM)
// W chunk:   [192][stride 104] bf16, 96 k per chunk, hi + lo
// ---------------------------------------------------------------------------
constexpr int SA = 200;                      // A row stride (elems)
constexpr int SW = 104;                      // W row stride (elems)
constexpr int A_OFF   = 1024;
constexpr int ASPL_B  = 128 * SA * 2;        // 51200 bytes per split
constexpr int W_OFF   = A_OFF + 2 * ASPL_B;  // 103424
constexpr int WSPL_B  = HDIM * SW * 2;       // 39936 bytes per split
constexpr int TC_SMEM = W_OFF + 2 * WSPL_B;  // 183296

template <int MODE>
__global__ __launch_bounds__(256) void tcmlp_kernel(
    int M,
    const float* __restrict__ s0r, const float* __restrict__ s0i,
    const float* __restrict__ s1r, const float* __restrict__ s1i,
    const float* __restrict__ s2r, const float* __restrict__ s2i,
    const void* __restrict__ eidx,
    const __nv_bfloat16* __restrict__ WhidH, const __nv_bfloat16* __restrict__ WhidL,
    const __nv_bfloat16* __restrict__ WoutH, const __nv_bfloat16* __restrict__ WoutL,
    const float* __restrict__ B, const float* __restrict__ alpha,
    const float* __restrict__ bout,
    float* __restrict__ outR, float* __restrict__ outI)
{
    extern __shared__ char sm[];
    float* bias_s = (float*)sm;
    uint32_t smb    = smem_u32(sm);
    uint32_t aHi    = smb + A_OFF;
    uint32_t aLo    = aHi + ASPL_B;
    uint32_t wHi    = smb + W_OFF;
    uint32_t wLo    = wHi + WSPL_B;

    int tid  = threadIdx.x;
    int lane = tid & 31;
    int wid  = tid >> 5;
    int warp_m = wid >> 2;       // 0..1
    int warp_n = wid & 3;        // 0..3
    int r0   = blockIdx.x * 128;
    int Meff = 2 * M;

    // ---- first-layer activation fill: gather fp32 -> split -> smem ----
    for (int idx = tid; idx < 128 * 96; idx += 256) {
        int row = idx / 96;
        int k   = (idx - row * 96) * 2;
        float2 v = make_float2(0.f, 0.f);
        int gr_eff = r0 + row;
        if (gr_eff < Meff) {
            int ch = gr_eff >= M;
            int gr = ch ? gr_eff - M : gr_eff;
            int src = k >> 6, f = k & 63;
            if (MODE == 0) {
                const float* p = (src == 0) ? (ch ? s0i : s0r)
                               : (src == 1) ? (ch ? s1i : s1r)
                                            : (ch ? s2i : s2r);
                v = *(const float2*)(p + gr * 64 + f);
            } else {
                if (src == 0) {
                    const float* p = ch ? s0i : s0r;
                    v = *(const float2*)(p + gr * 64 + f);
                } else {
                    int node = eidx_get(eidx, 2 * gr + (src - 1)); // 1->row, 2->col
                    const float* p = ch ? s1i : s1r;
                    v = *(const float2*)(p + node * 64 + f);
                }
            }
        }
        uint16_t h0, l0, h1, l1;
        split_bf16(v.x, h0, l0);
        split_bf16(v.y, h1, l1);
        uint32_t off = (uint32_t)(row * SA + k) * 2;
        *(uint32_t*)(sm + A_OFF + off)          = (uint32_t)h1 << 16 | h0;
        *(uint32_t*)(sm + A_OFF + ASPL_B + off) = (uint32_t)l1 << 16 | l0;
    }
    __syncthreads();

    float acc[4][6][4];

    // ================= 3 hidden layers =================
    for (int l = 0; l < 3; l++) {
        const __nv_bfloat16* Wh = WhidH + l * HDIM * HDIM;
        const __nv_bfloat16* Wl = WhidL + l * HDIM * HDIM;
        if (tid < HDIM) bias_s[tid] = B[l * HDIM + tid];
        float al = alpha[l];
#pragma unroll
        for (int mt = 0; mt < 4; mt++)
#pragma unroll
            for (int nt = 0; nt < 6; nt++)
#pragma unroll
                for (int q = 0; q < 4; q++) acc[mt][nt][q] = 0.f;

        for (int kc = 0; kc < 2; kc++) {
            // fill W chunk [192][96] both splits
            for (int idx = tid; idx < HDIM * 48; idx += 256) {
                int n = idx / 48;
                int k = (idx - n * 48) * 2;
                uint32_t wh2 = *(const uint32_t*)(Wh + n * HDIM + kc * 96 + k);
                uint32_t wl2 = *(const uint32_t*)(Wl + n * HDIM + kc * 96 + k);
                uint32_t off = (uint32_t)(n * SW + k) * 2;
                *(uint32_t*)(sm + W_OFF + off)          = wh2;
                *(uint32_t*)(sm + W_OFF + WSPL_B + off) = wl2;
            }
            __syncthreads();
#pragma unroll
            for (int ks = 0; ks < 6; ks++) {
                int kA = kc * 96 + ks * 16;
                int kW = ks * 16;
                uint32_t bh[12], bl[12];
#pragma unroll
                for (int p = 0; p < 3; p++) {
                    int nrow = warp_n * 48 + p * 16 + (lane & 7) + ((lane >> 4) << 3);
                    int kb   = kW + (((lane >> 3) & 1) << 3);
                    uint32_t off = (uint32_t)(nrow * SW + kb) * 2;
                    ldsm4(&bh[p * 4], wHi + off);
                    ldsm4(&bl[p * 4], wLo + off);
                }
#pragma unroll
                for (int mt = 0; mt < 4; mt++) {
                    int arow = warp_m * 64 + mt * 16 + (lane & 7) + (((lane >> 3) & 1) << 3);
                    int kb   = kA + ((lane >> 4) << 3);
                    uint32_t off = (uint32_t)(arow * SA + kb) * 2;
                    uint32_t ah4[4], al4[4];
                    ldsm4(ah4, aHi + off);
                    ldsm4(al4, aLo + off);
#pragma unroll
                    for (int nt = 0; nt < 6; nt++) {
                        mma16816(acc[mt][nt], ah4, &bh[nt * 2]);
                        mma16816(acc[mt][nt], ah4, &bl[nt * 2]);
                        mma16816(acc[mt][nt], al4, &bh[nt * 2]);
                    }
                }
            }
            __syncthreads();
        }

        // ---- epilogue: bias + leaky -> split -> back into A (in place) ----
#pragma unroll
        for (int mt = 0; mt < 4; mt++) {
            int rbase = warp_m * 64 + mt * 16 + (lane >> 2);
#pragma unroll
            for (int nt = 0; nt < 6; nt++) {
                int col = warp_n * 48 + nt * 8 + (lane & 3) * 2;
                float b0 = bias_s[col], b1 = bias_s[col + 1];
#pragma unroll
                for (int h = 0; h < 2; h++) {
                    float v0 = acc[mt][nt][2 * h]     + b0;
                    float v1 = acc[mt][nt][2 * h + 1] + b1;
                    v0 = (v0 >= 0.f) ? v0 : al * v0;
                    v1 = (v1 >= 0.f) ? v1 : al * v1;
                    uint16_t h0, l0, h1, l1;
                    split_bf16(v0, h0, l0);
                    split_bf16(v1, h1, l1);
                    int row = rbase + h * 8;
                    uint32_t off = (uint32_t)(row * SA + col) * 2;
                    *(uint32_t*)(sm + A_OFF + off)          = (uint32_t)h1 << 16 | h0;
                    *(uint32_t*)(sm + A_OFF + ASPL_B + off) = (uint32_t)l1 << 16 | l0;
                }
            }
        }
        __syncthreads();
    }

    // ================= output layer 192 -> 64 =================
    if (tid < OUTF) bias_s[tid] = bout[tid];
#pragma unroll
    for (int mt = 0; mt < 4; mt++)
#pragma unroll
        for (int nt = 0; nt < 2; nt++)
#pragma unroll
            for (int q = 0; q < 4; q++) acc[mt][nt][q] = 0.f;

    for (int kc = 0; kc < 2; kc++) {
        for (int idx = tid; idx < OUTF * 48; idx += 256) {
            int n = idx / 48;
            int k = (idx - n * 48) * 2;
            uint32_t wh2 = *(const uint32_t*)(WoutH + n * HDIM + kc * 96 + k);
            uint32_t wl2 = *(const uint32_t*)(WoutL + n * HDIM + kc * 96 + k);
            uint32_t off = (uint32_t)(n * SW + k) * 2;
            *(uint32_t*)(sm + W_OFF + off)          = wh2;
            *(uint32_t*)(sm + W_OFF + WSPL_B + off) = wl2;
        }
        __syncthreads();
#pragma unroll
        for (int ks = 0; ks < 6; ks++) {
            int kA = kc * 96 + ks * 16;
            int kW = ks * 16;
            uint32_t bh[4], bl[4];
            {
                int nrow = warp_n * 16 + (lane & 7) + ((lane >> 4) << 3);
                int kb   = kW + (((lane >> 3) & 1) << 3);
                uint32_t off = (uint32_t)(nrow * SW + kb) * 2;
                ldsm4(bh, wHi + off);
                ldsm4(bl, wLo + off);
            }
#pragma unroll
            for (int mt = 0; mt < 4; mt++) {
                int arow = warp_m * 64 + mt * 16 + (lane & 7) + (((lane >> 3) & 1) << 3);
                int kb   = kA + ((lane >> 4) << 3);
                uint32_t off = (uint32_t)(arow * SA + kb) * 2;
                uint32_t ah4[4], al4[4];
                ldsm4(ah4, aHi + off);
                ldsm4(al4, aLo + off);
#pragma unroll
                for (int nt = 0; nt < 2; nt++) {
                    mma16816(acc[mt][nt], ah4, &bh[nt * 2]);
                    mma16816(acc[mt][nt], ah4, &bl[nt * 2]);
                    mma16816(acc[mt][nt], al4, &bh[nt * 2]);
                }
            }
        }
        __syncthreads();
    }

    // ---- output epilogue -> gmem (float2 per thread per tile-half) ----
#pragma unroll
    for (int mt = 0; mt < 4; mt++) {
        int rbase = warp_m * 64 + mt * 16 + (lane >> 2);
#pragma unroll
        for (int nt = 0; nt < 2; nt++) {
            int col = warp_n * 16 + nt * 8 + (lane & 3) * 2;
            float b0 = bias_s[col], b1 = bias_s[col + 1];
#pragma unroll
            for (int h = 0; h < 2; h++) {
                int row = rbase + h * 8;
                int gr_eff = r0 + row;
                if (gr_eff < Meff) {
                    int ch = gr_eff >= M;
                    int gr = ch ? gr_eff - M : gr_eff;
                    float2 v;
                    v.x = acc[mt][nt][2 * h]     + b0;
                    v.y = acc[mt][nt][2 * h + 1] + b1;
                    *(float2*)((ch ? outI : outR) + gr * 64 + col) = v;
                }
            }
        }
    }
}

// ---------------------------------------------------------------------------
// launch
// ---------------------------------------------------------------------------
extern "C" void kernel_launch(void* const* d_in, const int* in_sizes, int n_in,
                              void* d_out, int out_size)
{
    const float* node_real = (const float*)d_in[0];
    const float* node_imag = (const float*)d_in[1];
    const float* edge_real = (const float*)d_in[2];
    const float* edge_imag = (const float*)d_in[3];
    const void*  edge_index = d_in[4];
    const float* Wn = (const float*)d_in[5];
    const float* bn = (const float*)d_in[6];
    const float* We = (const float*)d_in[7];
    const float* be = (const float*)d_in[8];
    const float* node_W    = (const float*)d_in[9];
    const float* node_b    = (const float*)d_in[10];
    const float* node_alpha= (const float*)d_in[11];
    const float* node_outW = (const float*)d_in[12];
    const float* node_outb = (const float*)d_in[13];
    const float* edge_W    = (const float*)d_in[14];
    const float* edge_b    = (const float*)d_in[15];
    const float* edge_alpha= (const float*)d_in[16];
    const float* edge_outW = (const float*)d_in[17];
    const float* edge_outb = (const float*)d_in[18];

    int Nn = in_sizes[0] / 64;
    int Ne = in_sizes[2] / 64;

    float* scratch = nullptr;
    cudaGetSymbolAddress((void**)&scratch, g_scratch);
    __nv_bfloat16* wh = nullptr;
    __nv_bfloat16* wl = nullptr;
    cudaGetSymbolAddress((void**)&wh, g_wh);
    cudaGetSymbolAddress((void**)&wl, g_wl);

    float* nr  = scratch + OFF_NR;
    float* ni  = scratch + OFF_NI;
    float* er  = scratch + OFF_ER;
    float* ei  = scratch + OFF_EI;
    float* nsr = scratch + OFF_NSR;
    float* esr = scratch + OFF_ESR;
    float* nsi = scratch + OFF_NSI;
    float* esi = scratch + OFF_ESI;

    float* outp = (float*)d_out;
    float* hr   = outp;
    float* hi   = outp + (size_t)Nn * 64;
    float* outr = outp + (size_t)2 * Nn * 64;
    float* outi = outr + (size_t)Ne * 64;

    cudaFuncSetAttribute(lin64_kernel, cudaFuncAttributeMaxDynamicSharedMemorySize, LIN_SMEM);
    cudaFuncSetAttribute(tcmlp_kernel<0>, cudaFuncAttributeMaxDynamicSharedMemorySize, TC_SMEM);
    cudaFuncSetAttribute(tcmlp_kernel<1>, cudaFuncAttributeMaxDynamicSharedMemorySize, TC_SMEM);

    // 1) edge_index dtype
    detect_kernel<<<1, 32>>>((const unsigned int*)edge_index);

    // 2) zero aggregation region
    int aggN4 = (int)(4 * (size_t)NN_MAX * 64 / 4);
    zero_kernel<<<(aggN4 + 255) / 256, 256>>>((float4*)nsr, aggN4);

    // 3) weight bf16 hi/lo pre-conversion
    wconv_kernel<<<(WTOT + 255) / 256, 256>>>(node_W, node_outW, edge_W, edge_outW);

    // 4) input linears
    lin64_kernel<<<(Nn + 63) / 64, 256, LIN_SMEM>>>(Nn, node_real, node_imag, Wn, bn, nr, ni);
    lin64_kernel<<<(Ne + 63) / 64, 256, LIN_SMEM>>>(Ne, edge_real, edge_imag, We, be, er, ei);

    // 5) edge scatter-aggregation
    int sthreads = Ne * 16;
    scatter_kernel<<<(sthreads + 255) / 256, 256>>>(Ne, edge_index, nr, ni, er, ei,
                                                    nsr, esr, nsi, esi);

    // 6) node MLP (mma.sync tensor cores) -> hr, hi
    int gn = (2 * Nn + 127) / 128;
    tcmlp_kernel<0><<<gn, 256, TC_SMEM>>>(
        Nn, nr, ni, nsr, nsi, esr, esi, nullptr,
        wh + WOFF_NODE_HID, wl + WOFF_NODE_HID,
        wh + WOFF_NODE_OUT, wl + WOFF_NODE_OUT,
        node_b, node_alpha, node_outb, hr, hi);

    // 7) edge MLP (mma.sync tensor cores) -> outr, outi
    int ge = (2 * Ne + 127) / 128;
    tcmlp_kernel<1><<<ge, 256, TC_SMEM>>>(
        Ne, er, ei, hr, hi, hr, hi, edge_index,
        wh + WOFF_EDGE_HID, wl + WOFF_EDGE_HID,
        wh + WOFF_EDGE_OUT, wl + WOFF_EDGE_OUT,
        edge_b, edge_alpha, edge_outb, outr, outi);
}

// round 15
// speedup vs baseline: 3.7937x; 1.1427x over previous
#include <cuda_runtime.h>
#include <cuda_bf16.h>
#include <cstdint>

// ---------------------------------------------------------------------------
// Problem constants
// ---------------------------------------------------------------------------
#define NN_MAX 25000
#define NE_MAX 200000
#define HDIM   192
#define OUTF   64

// scratch layout (floats)
constexpr size_t OFF_NR  = 0;
constexpr size_t OFF_NI  = OFF_NR  + (size_t)NN_MAX * 64;
constexpr size_t OFF_ER  = OFF_NI  + (size_t)NN_MAX * 64;
constexpr size_t OFF_EI  = OFF_ER  + (size_t)NE_MAX * 64;
constexpr size_t OFF_NSR = OFF_EI  + (size_t)NE_MAX * 64;
constexpr size_t OFF_ESR = OFF_NSR + (size_t)NN_MAX * 64;
constexpr size_t OFF_NSI = OFF_ESR + (size_t)NN_MAX * 64;
constexpr size_t OFF_ESI = OFF_NSI + (size_t)NN_MAX * 64;
constexpr size_t SCRATCH_FLOATS = OFF_ESI + (size_t)NN_MAX * 64;

__device__ __align__(256) float g_scratch[SCRATCH_FLOATS];
__device__ int g_is64;

// pre-converted bf16 weights (hi / lo split), [out][in] row-major
constexpr int WOFF_NODE_HID = 0;
constexpr int WOFF_NODE_OUT = WOFF_NODE_HID + 3 * HDIM * HDIM;
constexpr int WOFF_EDGE_HID = WOFF_NODE_OUT + OUTF * HDIM;
constexpr int WOFF_EDGE_OUT = WOFF_EDGE_HID + 3 * HDIM * HDIM;
constexpr int WTOT          = WOFF_EDGE_OUT + OUTF * HDIM;

__device__ __align__(256) __nv_bfloat16 g_wh[WTOT];
__device__ __align__(256) __nv_bfloat16 g_wl[WTOT];

// ---------------------------------------------------------------------------
// helpers
// ---------------------------------------------------------------------------
__device__ __forceinline__ unsigned long long pack2(float a, float b) {
    unsigned long long r;
    asm("mov.b64 %0, {%1,%2};" : "=l"(r) : "f"(a), "f"(b));
    return r;
}
__device__ __forceinline__ void unpack2(unsigned long long v, float& a, float& b) {
    asm("mov.b64 {%0,%1}, %2;" : "=f"(a), "=f"(b) : "l"(v));
}
__device__ __forceinline__ void fma2(unsigned long long& d,
                                     unsigned long long a, unsigned long long b) {
    asm("fma.rn.f32x2 %0, %1, %2, %0;" : "+l"(d) : "l"(a), "l"(b));
}
__device__ __forceinline__ void red_add_v4(float* p, float4 v) {
    asm volatile("red.global.add.v4.f32 [%0], {%1,%2,%3,%4};"
                 :: "l"(p), "f"(v.x), "f"(v.y), "f"(v.z), "f"(v.w) : "memory");
}
__device__ __forceinline__ uint32_t smem_u32(const void* p) {
    uint32_t a;
    asm("{ .reg .u64 t; cvta.to.shared.u64 t, %1; cvt.u32.u64 %0, t; }"
        : "=r"(a) : "l"(p));
    return a;
}
__device__ __forceinline__ void split_bf16(float v, uint16_t& h, uint16_t& l) {
    __nv_bfloat16 hb = __float2bfloat16_rn(v);
    float r = v - __bfloat162float(hb);
    __nv_bfloat16 lb = __float2bfloat16_rn(r);
    h = __bfloat16_as_ushort(hb);
    l = __bfloat16_as_ushort(lb);
}
// warp-level tensor ops (portable PTX, no sm_103a-only features)
__device__ __forceinline__ void ldsm4(uint32_t* r, uint32_t addr) {
    asm volatile("ldmatrix.sync.aligned.m8n8.x4.shared.b16 {%0,%1,%2,%3}, [%4];"
                 : "=r"(r[0]), "=r"(r[1]), "=r"(r[2]), "=r"(r[3]) : "r"(addr));
}
__device__ __forceinline__ void mma16816(float* d, const uint32_t* a, const uint32_t* b) {
    asm volatile("mma.sync.aligned.m16n8k16.row.col.f32.bf16.bf16.f32 "
                 "{%0,%1,%2,%3}, {%4,%5,%6,%7}, {%8,%9}, {%0,%1,%2,%3};"
                 : "+f"(d[0]), "+f"(d[1]), "+f"(d[2]), "+f"(d[3])
                 : "r"(a[0]), "r"(a[1]), "r"(a[2]), "r"(a[3]), "r"(b[0]), "r"(b[1]));
}
__device__ __forceinline__ void cpa16(uint32_t saddr, const void* g) {
    asm volatile("cp.async.cg.shared.global [%0], [%1], 16;"
                 :: "r"(saddr), "l"(g) : "memory");
}
#define CPA_COMMIT() asm volatile("cp.async.commit_group;" ::: "memory")
#define CPA_WAIT0()  asm volatile("cp.async.wait_group 0;" ::: "memory")

// ---------------------------------------------------------------------------
// edge_index dtype detection (int64 vs int32)
// ---------------------------------------------------------------------------
__global__ void detect_kernel(const unsigned int* __restrict__ w) {
    unsigned int v = w[2 * threadIdx.x + 1] | w[2 * threadIdx.x + 65];
    unsigned int any = __ballot_sync(0xffffffffu, v != 0u);
    if (threadIdx.x == 0) g_is64 = (any == 0u) ? 1 : 0;
}
__device__ __forceinline__ int eidx_get(const void* __restrict__ p, int i) {
    if (g_is64) return (int)((const long long*)p)[i];
    return ((const int*)p)[i];
}

// ---------------------------------------------------------------------------
// zero aggregation buffers
// ---------------------------------------------------------------------------
__global__ void zero_kernel(float4* __restrict__ p, int n4) {
    int i = blockIdx.x * blockDim.x + threadIdx.x;
    if (i < n4) p[i] = make_float4(0.f, 0.f, 0.f, 0.f);
}

// ---------------------------------------------------------------------------
// weight pre-conversion: fp32 -> bf16 hi/lo
// ---------------------------------------------------------------------------
__global__ void wconv_kernel(const float* __restrict__ nW, const float* __restrict__ nOW,
                             const float* __restrict__ eW, const float* __restrict__ eOW)
{
    int idx = blockIdx.x * blockDim.x + threadIdx.x;
    if (idx >= WTOT) return;
    float v;
    if (idx < WOFF_NODE_OUT)      v = nW[idx - WOFF_NODE_HID];
    else if (idx < WOFF_EDGE_HID) v = nOW[idx - WOFF_NODE_OUT];
    else if (idx < WOFF_EDGE_OUT) v = eW[idx - WOFF_EDGE_HID];
    else                          v = eOW[idx - WOFF_EDGE_OUT];
    uint16_t h, l;
    split_bf16(v, h, l);
    g_wh[idx] = __ushort_as_bfloat16(h);
    g_wl[idx] = __ushort_as_bfloat16(l);
}

// ---------------------------------------------------------------------------
// lin64 (proven, unchanged)
// ---------------------------------------------------------------------------
constexpr int LIN_SMEM = 64 * 64 * 8 + 64 * 65 * 4;

__global__ __launch_bounds__(256) void lin64_kernel(
    int M,
    const float* __restrict__ Xa, const float* __restrict__ Xb,
    const float* __restrict__ W,  const float* __restrict__ bias,
    float* __restrict__ Ya, float* __restrict__ Yb)
{
    extern __shared__ char smraw[];
    unsigned long long* Xs = (unsigned long long*)smraw;   // [64][64]
    float* Ws = (float*)(Xs + 64 * 64);                    // [64][65]

    int tid = threadIdx.x;
    int r0  = blockIdx.x * 64;

    for (int i = tid; i < 4096; i += 256) {
        int n = i >> 6, k = i & 63;
        Ws[n * 65 + k] = W[i];
    }
    for (int i = tid; i < 4096; i += 256) {
        int r = i >> 6, k = i & 63, gr = r0 + r;
        float a = 0.f, b = 0.f;
        if (gr < M) { a = Xa[gr * 64 + k]; b = Xb[gr * 64 + k]; }
        Xs[i] = pack2(a, b);
    }
    __syncthreads();

    int tx = tid & 15, ty = tid >> 4;
    unsigned long long acc[4][4];
#pragma unroll
    for (int j = 0; j < 4; j++) {
        float bv = bias[tx + 16 * j];
        unsigned long long pb = pack2(bv, bv);
#pragma unroll
        for (int i = 0; i < 4; i++) acc[i][j] = pb;
    }

#pragma unroll 8
    for (int k = 0; k < 64; k++) {
        unsigned long long xv[4], wv[4];
#pragma unroll
        for (int i = 0; i < 4; i++) xv[i] = Xs[(ty * 4 + i) * 64 + k];
#pragma unroll
        for (int j = 0; j < 4; j++) {
            float w = Ws[(tx + 16 * j) * 65 + k];
            wv[j] = pack2(w, w);
        }
#pragma unroll
        for (int i = 0; i < 4; i++)
#pragma unroll
            for (int j = 0; j < 4; j++) fma2(acc[i][j], xv[i], wv[j]);
    }

#pragma unroll
    for (int i = 0; i < 4; i++) {
        int gr = r0 + ty * 4 + i;
        if (gr < M) {
#pragma unroll
            for (int j = 0; j < 4; j++) {
                float a, b;
                unpack2(acc[i][j], a, b);
                Ya[gr * 64 + tx + 16 * j] = a;
                Yb[gr * 64 + tx + 16 * j] = b;
            }
        }
    }
}

// ---------------------------------------------------------------------------
// scatter (proven, unchanged)
// ---------------------------------------------------------------------------
__global__ __launch_bounds__(256) void scatter_kernel(
    int NE, const void* __restrict__ eidx,
    const float* __restrict__ nr, const float* __restrict__ ni,
    const float* __restrict__ er, const float* __restrict__ ei,
    float* __restrict__ nsr, float* __restrict__ esr,
    float* __restrict__ nsi, float* __restrict__ esi)
{
    int gid = blockIdx.x * blockDim.x + threadIdx.x;
    int e = gid >> 4;
    if (e >= NE) return;
    int q = (gid & 15) * 4;
    int row = eidx_get(eidx, 2 * e);
    int col = eidx_get(eidx, 2 * e + 1);

    const float4 a = *(const float4*)(nr + col * 64 + q);
    const float4 b = *(const float4*)(er + e   * 64 + q);
    const float4 c = *(const float4*)(ni + col * 64 + q);
    const float4 d = *(const float4*)(ei + e   * 64 + q);

    red_add_v4(nsr + row * 64 + q, a);
    red_add_v4(esr + row * 64 + q, b);
    red_add_v4(nsi + row * 64 + q, c);
    red_add_v4(esi + row * 64 + q, d);
}

// ---------------------------------------------------------------------------
// mma.sync fused MLP with cp.async double-buffered weight pipeline.
// 3x(192->192 + LeakyReLU) + (192->64); bf16 hi/lo split; fp32 accum.
// Tile = 128 rows of Meff=2*M. 8 warps as 2(m) x 4(n); warp tile 64x48.
// A in smem: [128][stride 200] bf16, hi + lo planes (conflict-free LDSM)
// W: 48-k chunks [rows][stride 56] bf16 hi+lo, double buffered (cp.async)
// ---------------------------------------------------------------------------
constexpr int SA = 200;                       // A row stride (elems)
constexpr int SW = 56;                        // W chunk row stride (elems)
constexpr int A_OFF   = 1024;
constexpr int ASPL_B  = 128 * SA * 2;         // 51200 bytes per split
constexpr int W_OFF   = A_OFF + 2 * ASPL_B;   // 103424
constexpr int WSPL_B  = HDIM * SW * 2;        // 21504 bytes per split
constexpr int WBUF_B  = 2 * WSPL_B;           // 43008 per buffer (hi+lo)
constexpr int TC_SMEM = W_OFF + 2 * WBUF_B;   // 189440

template <int MODE>
__global__ __launch_bounds__(256) void tcmlp_kernel(
    int M,
    const float* __restrict__ s0r, const float* __restrict__ s0i,
    const float* __restrict__ s1r, const float* __restrict__ s1i,
    const float* __restrict__ s2r, const float* __restrict__ s2i,
    const void* __restrict__ eidx,
    const __nv_bfloat16* __restrict__ WhidH, const __nv_bfloat16* __restrict__ WhidL,
    const __nv_bfloat16* __restrict__ WoutH, const __nv_bfloat16* __restrict__ WoutL,
    const float* __restrict__ B, const float* __restrict__ alpha,
    const float* __restrict__ bout,
    float* __restrict__ outR, float* __restrict__ outI)
{
    extern __shared__ char sm[];
    float* bias_s = (float*)sm;
    uint32_t smb = smem_u32(sm);
    uint32_t aHi = smb + A_OFF;
    uint32_t aLo = aHi + ASPL_B;

    int tid  = threadIdx.x;
    int lane = tid & 31;
    int wid  = tid >> 5;
    int warp_m = wid >> 2;       // 0..1
    int warp_n = wid & 3;        // 0..3
    int r0   = blockIdx.x * 128;
    int Meff = 2 * M;

    // ---- first-layer activation fill: gather fp32 -> split -> smem ----
    for (int idx = tid; idx < 128 * 96; idx += 256) {
        int row = idx / 96;
        int k   = (idx - row * 96) * 2;
        float2 v = make_float2(0.f, 0.f);
        int gr_eff = r0 + row;
        if (gr_eff < Meff) {
            int ch = gr_eff >= M;
            int gr = ch ? gr_eff - M : gr_eff;
            int src = k >> 6, f = k & 63;
            if (MODE == 0) {
                const float* p = (src == 0) ? (ch ? s0i : s0r)
                               : (src == 1) ? (ch ? s1i : s1r)
                                            : (ch ? s2i : s2r);
                v = *(const float2*)(p + gr * 64 + f);
            } else {
                if (src == 0) {
                    const float* p = ch ? s0i : s0r;
                    v = *(const float2*)(p + gr * 64 + f);
                } else {
                    int node = eidx_get(eidx, 2 * gr + (src - 1)); // 1->row, 2->col
                    const float* p = ch ? s1i : s1r;
                    v = *(const float2*)(p + node * 64 + f);
                }
            }
        }
        uint16_t h0, l0, h1, l1;
        split_bf16(v.x, h0, l0);
        split_bf16(v.y, h1, l1);
        uint32_t off = (uint32_t)(row * SA + k) * 2;
        *(uint32_t*)(sm + A_OFF + off)          = (uint32_t)h1 << 16 | h0;
        *(uint32_t*)(sm + A_OFF + ASPL_B + off) = (uint32_t)l1 << 16 | l0;
    }

    float acc[4][6][4];

    // ================= 3 hidden layers =================
    for (int l = 0; l < 3; l++) {
        const __nv_bfloat16* Wh = WhidH + l * HDIM * HDIM;
        const __nv_bfloat16* Wl = WhidL + l * HDIM * HDIM;
        if (tid < HDIM) bias_s[tid] = B[l * HDIM + tid];
        float al = alpha[l];
#pragma unroll
        for (int mt = 0; mt < 4; mt++)
#pragma unroll
            for (int nt = 0; nt < 6; nt++)
#pragma unroll
                for (int q = 0; q < 4; q++) acc[mt][nt][q] = 0.f;

        // prefetch chunk 0
        {
            uint32_t bHiS = smb + W_OFF, bLoS = bHiS + WSPL_B;
            for (int idx = tid; idx < HDIM * 6; idx += 256) {
                int n = idx / 6, j = idx - n * 6;
                uint32_t so = (uint32_t)(n * SW + j * 8) * 2;
                int go = n * HDIM + j * 8;
                cpa16(bHiS + so, Wh + go);
                cpa16(bLoS + so, Wl + go);
            }
            CPA_COMMIT();
        }

        for (int kc = 0; kc < 4; kc++) {
            CPA_WAIT0();
            __syncthreads();    // chunk kc ready; all warps done with other buffer
            if (kc < 3) {       // prefetch next chunk into other buffer (overlaps MMA)
                uint32_t bHiS = smb + W_OFF + ((kc + 1) & 1) * WBUF_B;
                uint32_t bLoS = bHiS + WSPL_B;
                for (int idx = tid; idx < HDIM * 6; idx += 256) {
                    int n = idx / 6, j = idx - n * 6;
                    uint32_t so = (uint32_t)(n * SW + j * 8) * 2;
                    int go = n * HDIM + (kc + 1) * 48 + j * 8;
                    cpa16(bHiS + so, Wh + go);
                    cpa16(bLoS + so, Wl + go);
                }
                CPA_COMMIT();
            }
            uint32_t wHi = smb + W_OFF + (kc & 1) * WBUF_B;
            uint32_t wLo = wHi + WSPL_B;
#pragma unroll
            for (int ks = 0; ks < 3; ks++) {
                int kA = kc * 48 + ks * 16;
                int kW = ks * 16;
                uint32_t bh[12], bl[12];
#pragma unroll
                for (int p = 0; p < 3; p++) {
                    int nrow = warp_n * 48 + p * 16 + (lane & 7) + ((lane >> 4) << 3);
                    int kb   = kW + (((lane >> 3) & 1) << 3);
                    uint32_t off = (uint32_t)(nrow * SW + kb) * 2;
                    ldsm4(&bh[p * 4], wHi + off);
                    ldsm4(&bl[p * 4], wLo + off);
                }
#pragma unroll
                for (int mt = 0; mt < 4; mt++) {
                    int arow = warp_m * 64 + mt * 16 + (lane & 7) + (((lane >> 3) & 1) << 3);
                    int kb   = kA + ((lane >> 4) << 3);
                    uint32_t off = (uint32_t)(arow * SA + kb) * 2;
                    uint32_t ah4[4], al4[4];
                    ldsm4(ah4, aHi + off);
                    ldsm4(al4, aLo + off);
#pragma unroll
                    for (int nt = 0; nt < 6; nt++) {
                        mma16816(acc[mt][nt], ah4, &bh[nt * 2]);
                        mma16816(acc[mt][nt], ah4, &bl[nt * 2]);
                        mma16816(acc[mt][nt], al4, &bh[nt * 2]);
                    }
                }
            }
        }
        __syncthreads();   // all warps done reading A before in-place rewrite

        // ---- epilogue: bias + leaky -> split -> back into A (in place) ----
#pragma unroll
        for (int mt = 0; mt < 4; mt++) {
            int rbase = warp_m * 64 + mt * 16 + (lane >> 2);
#pragma unroll
            for (int nt = 0; nt < 6; nt++) {
                int col = warp_n * 48 + nt * 8 + (lane & 3) * 2;
                float b0 = bias_s[col], b1 = bias_s[col + 1];
#pragma unroll
                for (int h = 0; h < 2; h++) {
                    float v0 = acc[mt][nt][2 * h]     + b0;
                    float v1 = acc[mt][nt][2 * h + 1] + b1;
                    v0 = (v0 >= 0.f) ? v0 : al * v0;
                    v1 = (v1 >= 0.f) ? v1 : al * v1;
                    uint16_t h0, l0, h1, l1;
                    split_bf16(v0, h0, l0);
                    split_bf16(v1, h1, l1);
                    int row = rbase + h * 8;
                    uint32_t off = (uint32_t)(row * SA + col) * 2;
                    *(uint32_t*)(sm + A_OFF + off)          = (uint32_t)h1 << 16 | h0;
                    *(uint32_t*)(sm + A_OFF + ASPL_B + off) = (uint32_t)l1 << 16 | l0;
                }
            }
        }
        __syncthreads();
    }

    // ================= output layer 192 -> 64 =================
    if (tid < OUTF) bias_s[tid] = bout[tid];
#pragma unroll
    for (int mt = 0; mt < 4; mt++)
#pragma unroll
        for (int nt = 0; nt < 2; nt++)
#pragma unroll
            for (int q = 0; q < 4; q++) acc[mt][nt][q] = 0.f;

    // prefetch chunk 0
    {
        uint32_t bHiS = smb + W_OFF, bLoS = bHiS + WSPL_B;
        for (int idx = tid; idx < OUTF * 6; idx += 256) {
            int n = idx / 6, j = idx - n * 6;
            uint32_t so = (uint32_t)(n * SW + j * 8) * 2;
            int go = n * HDIM + j * 8;
            cpa16(bHiS + so, WoutH + go);
            cpa16(bLoS + so, WoutL + go);
        }
        CPA_COMMIT();
    }

    for (int kc = 0; kc < 4; kc++) {
        CPA_WAIT0();
        __syncthreads();
        if (kc < 3) {
            uint32_t bHiS = smb + W_OFF + ((kc + 1) & 1) * WBUF_B;
            uint32_t bLoS = bHiS + WSPL_B;
            for (int idx = tid; idx < OUTF * 6; idx += 256) {
                int n = idx / 6, j = idx - n * 6;
                uint32_t so = (uint32_t)(n * SW + j * 8) * 2;
                int go = n * HDIM + (kc + 1) * 48 + j * 8;
                cpa16(bHiS + so, WoutH + go);
                cpa16(bLoS + so, WoutL + go);
            }
            CPA_COMMIT();
        }
        uint32_t wHi = smb + W_OFF + (kc & 1) * WBUF_B;
        uint32_t wLo = wHi + WSPL_B;
#pragma unroll
        for (int ks = 0; ks < 3; ks++) {
            int kA = kc * 48 + ks * 16;
            int kW = ks * 16;
            uint32_t bh[4], bl[4];
            {
                int nrow = warp_n * 16 + (lane & 7) + ((lane >> 4) << 3);
                int kb   = kW + (((lane >> 3) & 1) << 3);
                uint32_t off = (uint32_t)(nrow * SW + kb) * 2;
                ldsm4(bh, wHi + off);
                ldsm4(bl, wLo + off);
            }
#pragma unroll
            for (int mt = 0; mt < 4; mt++) {
                int arow = warp_m * 64 + mt * 16 + (lane & 7) + (((lane >> 3) & 1) << 3);
                int kb   = kA + ((lane >> 4) << 3);
                uint32_t off = (uint32_t)(arow * SA + kb) * 2;
                uint32_t ah4[4], al4[4];
                ldsm4(ah4, aHi + off);
                ldsm4(al4, aLo + off);
#pragma unroll
                for (int nt = 0; nt < 2; nt++) {
                    mma16816(acc[mt][nt], ah4, &bh[nt * 2]);
                    mma16816(acc[mt][nt], ah4, &bl[nt * 2]);
                    mma16816(acc[mt][nt], al4, &bh[nt * 2]);
                }
            }
        }
    }

    // ---- output epilogue -> gmem (float2 per thread per tile-half) ----
#pragma unroll
    for (int mt = 0; mt < 4; mt++) {
        int rbase = warp_m * 64 + mt * 16 + (lane >> 2);
#pragma unroll
        for (int nt = 0; nt < 2; nt++) {
            int col = warp_n * 16 + nt * 8 + (lane & 3) * 2;
            float b0 = bias_s[col], b1 = bias_s[col + 1];
#pragma unroll
            for (int h = 0; h < 2; h++) {
                int row = rbase + h * 8;
                int gr_eff = r0 + row;
                if (gr_eff < Meff) {
                    int ch = gr_eff >= M;
                    int gr = ch ? gr_eff - M : gr_eff;
                    float2 v;
                    v.x = acc[mt][nt][2 * h]     + b0;
                    v.y = acc[mt][nt][2 * h + 1] + b1;
                    *(float2*)((ch ? outI : outR) + gr * 64 + col) = v;
                }
            }
        }
    }
}

// ---------------------------------------------------------------------------
// launch
// ---------------------------------------------------------------------------
extern "C" void kernel_launch(void* const* d_in, const int* in_sizes, int n_in,
                              void* d_out, int out_size)
{
    const float* node_real = (const float*)d_in[0];
    const float* node_imag = (const float*)d_in[1];
    const float* edge_real = (const float*)d_in[2];
    const float* edge_imag = (const float*)d_in[3];
    const void*  edge_index = d_in[4];
    const float* Wn = (const float*)d_in[5];
    const float* bn = (const float*)d_in[6];
    const float* We = (const float*)d_in[7];
    const float* be = (const float*)d_in[8];
    const float* node_W    = (const float*)d_in[9];
    const float* node_b    = (const float*)d_in[10];
    const float* node_alpha= (const float*)d_in[11];
    const float* node_outW = (const float*)d_in[12];
    const float* node_outb = (const float*)d_in[13];
    const float* edge_W    = (const float*)d_in[14];
    const float* edge_b    = (const float*)d_in[15];
    const float* edge_alpha= (const float*)d_in[16];
    const float* edge_outW = (const float*)d_in[17];
    const float* edge_outb = (const float*)d_in[18];

    int Nn = in_sizes[0] / 64;
    int Ne = in_sizes[2] / 64;

    float* scratch = nullptr;
    cudaGetSymbolAddress((void**)&scratch, g_scratch);
    __nv_bfloat16* wh = nullptr;
    __nv_bfloat16* wl = nullptr;
    cudaGetSymbolAddress((void**)&wh, g_wh);
    cudaGetSymbolAddress((void**)&wl, g_wl);

    float* nr  = scratch + OFF_NR;
    float* ni  = scratch + OFF_NI;
    float* er  = scratch + OFF_ER;
    float* ei  = scratch + OFF_EI;
    float* nsr = scratch + OFF_NSR;
    float* esr = scratch + OFF_ESR;
    float* nsi = scratch + OFF_NSI;
    float* esi = scratch + OFF_ESI;

    float* outp = (float*)d_out;
    float* hr   = outp;
    float* hi   = outp + (size_t)Nn * 64;
    float* outr = outp + (size_t)2 * Nn * 64;
    float* outi = outr + (size_t)Ne * 64;

    cudaFuncSetAttribute(lin64_kernel, cudaFuncAttributeMaxDynamicSharedMemorySize, LIN_SMEM);
    cudaFuncSetAttribute(tcmlp_kernel<0>, cudaFuncAttributeMaxDynamicSharedMemorySize, TC_SMEM);
    cudaFuncSetAttribute(tcmlp_kernel<1>, cudaFuncAttributeMaxDynamicSharedMemorySize, TC_SMEM);

    // 1) edge_index dtype
    detect_kernel<<<1, 32>>>((const unsigned int*)edge_index);

    // 2) zero aggregation region
    int aggN4 = (int)(4 * (size_t)NN_MAX * 64 / 4);
    zero_kernel<<<(aggN4 + 255) / 256, 256>>>((float4*)nsr, aggN4);

    // 3) weight bf16 hi/lo pre-conversion
    wconv_kernel<<<(WTOT + 255) / 256, 256>>>(node_W, node_outW, edge_W, edge_outW);

    // 4) input linears
    lin64_kernel<<<(Nn + 63) / 64, 256, LIN_SMEM>>>(Nn, node_real, node_imag, Wn, bn, nr, ni);
    lin64_kernel<<<(Ne + 63) / 64, 256, LIN_SMEM>>>(Ne, edge_real, edge_imag, We, be, er, ei);

    // 5) edge scatter-aggregation
    int sthreads = Ne * 16;
    scatter_kernel<<<(sthreads + 255) / 256, 256>>>(Ne, edge_index, nr, ni, er, ei,
                                                    nsr, esr, nsi, esi);

    // 6) node MLP (mma.sync tensor cores) -> hr, hi
    int gn = (2 * Nn + 127) / 128;
    tcmlp_kernel<0><<<gn, 256, TC_SMEM>>>(
        Nn, nr, ni, nsr, nsi, esr, esi, nullptr,
        wh + WOFF_NODE_HID, wl + WOFF_NODE_HID,
        wh + WOFF_NODE_OUT, wl + WOFF_NODE_OUT,
        node_b, node_alpha, node_outb, hr, hi);

    // 7) edge MLP (mma.sync tensor cores) -> outr, outi
    int ge = (2 * Ne + 127) / 128;
    tcmlp_kernel<1><<<ge, 256, TC_SMEM>>>(
        Ne, er, ei, hr, hi, hr, hi, edge_index,
        wh + WOFF_EDGE_HID, wl + WOFF_EDGE_HID,
        wh + WOFF_EDGE_OUT, wl + WOFF_EDGE_OUT,
        edge_b, edge_alpha, edge_outb, outr, outi);
}